// round 15
// baseline (speedup 1.0000x reference)
#include <cuda_runtime.h>
#include <cstdint>

#define THREADS 256

// ---- dynamic smem byte offsets ----
#define SB_B    0         // Bpack u32 [128 k2][56] = 28672 B; word k2*56+o*2+{0:hi,1:lo}
#define SB_A    28672     // 2 x 16384 B A slice buffers (hi 128 rows x 64 B, lo +8192)
#define SB_REI  28672     // overlay on A after GEMM (12288 B)
#define SB_AUG  40960     // overlay on A: 8 x 272 floats = 8704 B
#define SB_CST  61440     // S 3072 | EI 512 | BI 64
#define SMEM_BYTES 65088

// ---------- helpers ----------
__device__ __forceinline__ uint32_t smem_u32(const void* p) {
    uint32_t a;
    asm("{ .reg .u64 t; cvta.to.shared.u64 t, %1; cvt.u32.u64 %0, t; }" : "=r"(a) : "l"(p));
    return a;
}
__device__ __forceinline__ unsigned long long pk2(float lo, float hi) {
    unsigned long long r;
    asm("mov.b64 %0, {%1, %2};" : "=l"(r) : "f"(lo), "f"(hi));
    return r;
}
__device__ __forceinline__ void upk2(unsigned long long v, float& lo, float& hi) {
    asm("mov.b64 {%0, %1}, %2;" : "=f"(lo), "=f"(hi) : "l"(v));
}
__device__ __forceinline__ void ffma2(unsigned long long& acc, unsigned long long a, unsigned long long b) {
    asm("fma.rn.f32x2 %0, %1, %2, %0;" : "+l"(acc) : "l"(a), "l"(b));
}
__device__ __forceinline__ float sqrt_ap(float x){ float r; asm("sqrt.approx.f32 %0, %1;" : "=f"(r) : "f"(x)); return r; }
__device__ __forceinline__ float rcp_ap (float x){ float r; asm("rcp.approx.f32 %0, %1;"  : "=f"(r) : "f"(x)); return r; }

__device__ __forceinline__ void mma16816(float* d, uint32_t a0, uint32_t a1, uint32_t a2, uint32_t a3,
                                         uint32_t b0, uint32_t b1) {
    asm volatile(
        "mma.sync.aligned.m16n8k16.row.col.f32.bf16.bf16.f32 "
        "{%0,%1,%2,%3}, {%4,%5,%6,%7}, {%8,%9}, {%0,%1,%2,%3};"
        : "+f"(d[0]), "+f"(d[1]), "+f"(d[2]), "+f"(d[3])
        : "r"(a0), "r"(a1), "r"(a2), "r"(a3), "r"(b0), "r"(b1));
}
__device__ __forceinline__ void ldsm4(uint32_t& a0, uint32_t& a1, uint32_t& a2, uint32_t& a3, uint32_t addr) {
    asm volatile("ldmatrix.sync.aligned.m8n8.x4.shared.b16 {%0,%1,%2,%3}, [%4];"
                 : "=r"(a0), "=r"(a1), "=r"(a2), "=r"(a3) : "r"(addr));
}

// convert float4 -> bf16 hi uint2 + lo uint2
__device__ __forceinline__ void cvt_hilo(float4 x4, uint2& hv, uint2& lv) {
    uint32_t h01, h23;
    asm("cvt.rn.bf16x2.f32 %0, %1, %2;" : "=r"(h01) : "f"(x4.y), "f"(x4.x));
    asm("cvt.rn.bf16x2.f32 %0, %1, %2;" : "=r"(h23) : "f"(x4.w), "f"(x4.z));
    float f0 = __uint_as_float(h01 << 16), f1 = __uint_as_float(h01 & 0xFFFF0000u);
    float f2 = __uint_as_float(h23 << 16), f3 = __uint_as_float(h23 & 0xFFFF0000u);
    uint32_t l01, l23;
    asm("cvt.rn.bf16x2.f32 %0, %1, %2;" : "=r"(l01) : "f"(x4.y - f1), "f"(x4.x - f0));
    asm("cvt.rn.bf16x2.f32 %0, %1, %2;" : "=r"(l23) : "f"(x4.w - f3), "f"(x4.z - f2));
    hv.x = h01; hv.y = h23; lv.x = l01; lv.y = l23;
}

__global__ __launch_bounds__(THREADS, 3)
void ocae11(const float* __restrict__ eq,  const float* __restrict__ rei,
            const float* __restrict__ Wg,  const float* __restrict__ bias,
            const float* __restrict__ envdim, const float* __restrict__ envion,
            float* __restrict__ out)
{
    extern __shared__ __align__(16) unsigned char smem[];
    const uint32_t sb = smem_u32(smem);
    uint32_t* BPW = (uint32_t*)(smem + SB_B);
    float* Ssh = (float*)(smem + SB_CST);
    float* EIs = (float*)(smem + SB_CST + 3072);
    float* BIs = (float*)(smem + SB_CST + 3584);
    float* AUG = (float*)(smem + SB_AUG);

    const int tid  = threadIdx.x;
    const int wid  = tid >> 5;
    const int lane = tid & 31;
    const int s    = blockIdx.x & 1;
    const int b0   = (blockIdx.x >> 1) * 8;   // 8 batch-spins = 128 eq rows

    // -------- stage Bpack, stride 56 words: word k2*56 + o*2 + {0:hi, 1:lo} --------
    #pragma unroll
    for (int u = 0; u < 16; u++) {
        int idx = tid + 256 * u;              // 0..4095
        float w = __ldg(Wg + s * 4096 + idx);
        int k = idx >> 4, o = idx & 15;
        unsigned short hb; asm("cvt.rn.bf16.f32 %0, %1;" : "=h"(hb) : "f"(w));
        float hf = __uint_as_float(((uint32_t)hb) << 16);
        float lw = w - hf;
        unsigned short lb; asm("cvt.rn.bf16.f32 %0, %1;" : "=h"(lb) : "f"(lw));
        int byt = ((k >> 1) * 56 + o * 2) * 4 + (k & 1) * 2;
        *(unsigned short*)(smem + SB_B + byt)     = hb;
        *(unsigned short*)(smem + SB_B + byt + 4) = lb;
    }

    // -------- stage env constants --------
    if (tid < 128) {
        EIs[tid] = envion[s * 128 + tid];
        int ii = tid >> 4, oo = tid & 15;
        const float* A = envdim + s * 1152 + ii * 144 + oo * 9;
        float a00=A[0],a01=A[1],a02=A[2], a10=A[3],a11=A[4],a12=A[5], a20=A[6],a21=A[7],a22=A[8];
        float s00 = a00*a00 + a10*a10 + a20*a20;
        float s11 = a01*a01 + a11*a11 + a21*a21;
        float s22 = a02*a02 + a12*a12 + a22*a22;
        float s01 = 2.f*(a00*a01 + a10*a11 + a20*a21);
        float s02 = 2.f*(a00*a02 + a10*a12 + a20*a22);
        float s12 = 2.f*(a01*a02 + a11*a12 + a21*a22);
        float* dst = Ssh + (ii*8 + (oo>>1))*12 + (oo&1);
        dst[0]=s00; dst[2]=s11; dst[4]=s22; dst[6]=s01; dst[8]=s02; dst[10]=s12;
    }
    if (tid < 16) BIs[tid] = bias[s*16 + tid];

    // -------- A staging geometry: thread = (c = tid&7, rbq = (tid>>3)&15, jh = tid>>7); batches jh*4+u --------
    const int c   = tid & 7;
    const int rbq = (tid >> 3) & 15;
    const int jh  = tid >> 7;
    const float4* gpA[4];
    int soA[4];
    #pragma unroll
    for (int u = 0; u < 4; u++) {
        int j = jh * 4 + u;
        gpA[u] = (const float4*)(eq + ((size_t)(b0 + j) * 32 + s * 16 + rbq) * 256) + c;
        soA[u] = j * 1024 + rbq * 64 + ((((c >> 1) + (rbq >> 1)) & 3) << 4) + (c & 1) * 8;
    }

    float4 pre[4];
    #pragma unroll
    for (int u = 0; u < 4; u++) pre[u] = __ldg(gpA[u]);          // slice 0

    // store slice 0 -> buf0
    #pragma unroll
    for (int u = 0; u < 4; u++) {
        uint2 hv, lv; cvt_hilo(pre[u], hv, lv);
        *(uint2*)(smem + SB_A + soA[u])        = hv;
        *(uint2*)(smem + SB_A + soA[u] + 8192) = lv;
    }
    #pragma unroll
    for (int u = 0; u < 4; u++) pre[u] = __ldg(gpA[u] + 8);      // slice 1
    __syncthreads();                                             // consts + buf0 ready

    // -------- fragment geometry: warp wid owns matrix wid (rows 16wid..16wid+15) --------
    const int g  = lane >> 2;
    const int tg = lane & 3;
    const int ln = lane & 15;
    const int rowl = 16 * wid + ln;
    const int swq  = (lane >> 4) + (ln >> 1);

    float acc[2][4];
    #pragma unroll
    for (int b = 0; b < 2; b++)
        #pragma unroll
        for (int j2 = 0; j2 < 4; j2++) acc[b][j2] = 0.f;

    // -------- GEMM: 8 k32 slices, double-buffered, 1 barrier/slice --------
    #pragma unroll 1
    for (int sl = 0; sl < 8; sl++) {
        if (sl < 7) {
            unsigned char* bb = smem + SB_A + ((sl + 1) & 1) * 16384;
            #pragma unroll
            for (int u = 0; u < 4; u++) {
                uint2 hv, lv; cvt_hilo(pre[u], hv, lv);
                *(uint2*)(bb + soA[u])        = hv;
                *(uint2*)(bb + soA[u] + 8192) = lv;
            }
            if (sl < 6) {
                #pragma unroll
                for (int u = 0; u < 4; u++) pre[u] = __ldg(gpA[u] + (sl + 2) * 8);
            }
        }

        const uint32_t abase = sb + SB_A + (sl & 1) * 16384;
        #pragma unroll
        for (int ks = 0; ks < 2; ks++) {
            int k2 = sl * 16 + ks * 8 + tg;
            uint2 p0[2], p1[2];                 // {bh, bl} at k2 and k2+4
            #pragma unroll
            for (int nt = 0; nt < 2; nt++) {
                p0[nt] = *(const uint2*)(BPW + k2 * 56 + (8*nt + g) * 2);
                p1[nt] = *(const uint2*)(BPW + (k2 + 4) * 56 + (8*nt + g) * 2);
            }
            const uint32_t chunk = ((ks * 2 + swq) & 3) << 4;
            uint32_t rofs = rowl * 64 + chunk;
            uint32_t h0, h1, h2, h3, l0, l1, l2, l3;
            ldsm4(h0, h1, h2, h3, abase + rofs);
            ldsm4(l0, l1, l2, l3, abase + rofs + 8192);
            #pragma unroll
            for (int nt = 0; nt < 2; nt++) {
                mma16816(acc[nt], h0, h1, h2, h3, p0[nt].x, p1[nt].x);   // hi*hi
                mma16816(acc[nt], h0, h1, h2, h3, p0[nt].y, p1[nt].y);   // hi*lo
                mma16816(acc[nt], l0, l1, l2, l3, p0[nt].x, p1[nt].x);   // lo*hi
            }
        }
        __syncthreads();
    }

    // -------- stage rei into REI (overlays A) --------
    #pragma unroll
    for (int u = 0; u < 3; u++) {
        int f = tid + 256 * u;        // 0..767
        int rw = f / 6, q = f - rw * 6;
        size_t grow = ((size_t)(b0 + (rw >> 4))) * 32 + s * 16 + (rw & 15);
        *(float4*)(smem + SB_REI + (rw * 24 + q * 4) * 4) = __ldg((const float4*)rei + grow * 6 + q);
    }
    __syncthreads();

    // -------- y = acc + bias --------
    float y[2][4];
    #pragma unroll
    for (int nt = 0; nt < 2; nt++)
        #pragma unroll
        for (int j = 0; j < 4; j++)
            y[nt][j] = acc[nt][j] + BIs[8*nt + 2*tg + (j & 1)];

    // -------- env + M (2 rows per thread; 2 o-pairs per row); warp wid -> matrix wid --------
    #pragma unroll 1
    for (int rh = 0; rh < 2; rh++) {
        const int n = 8 * rh + g;               // row within matrix
        float rv[24];
        {
            const float* rp = (const float*)(smem + SB_REI) + (wid * 16 + n) * 24;
            #pragma unroll
            for (int q = 0; q < 6; q++) *(float4*)(rv + q * 4) = *(const float4*)(rp + q * 4);
        }
        unsigned long long ev[2] = {0ull, 0ull};
        #pragma unroll
        for (int i = 0; i < 8; i++) {
            float r0 = rv[i*3], r1 = rv[i*3+1], r2 = rv[i*3+2];
            unsigned long long p00 = pk2(r0*r0, r0*r0);
            unsigned long long p11 = pk2(r1*r1, r1*r1);
            unsigned long long p22 = pk2(r2*r2, r2*r2);
            unsigned long long p01 = pk2(r0*r1, r0*r1);
            unsigned long long p02 = pk2(r0*r2, r0*r2);
            unsigned long long p12 = pk2(r1*r2, r1*r2);
            #pragma unroll
            for (int nt = 0; nt < 2; nt++) {
                int op = 4 * nt + tg;
                const unsigned long long* Sp = (const unsigned long long*)(Ssh + (i*8 + op) * 12);
                unsigned long long q = 0ull;
                ffma2(q, Sp[0], p00); ffma2(q, Sp[1], p11); ffma2(q, Sp[2], p22);
                ffma2(q, Sp[3], p01); ffma2(q, Sp[4], p02); ffma2(q, Sp[5], p12);
                float q0, q1; upk2(q, q0, q1);
                float e0 = __expf(-sqrt_ap(fmaxf(q0, 0.f)));
                float e1 = __expf(-sqrt_ap(fmaxf(q1, 0.f)));
                ffma2(ev[nt], pk2(e0, e1), *((const unsigned long long*)EIs + i*8 + op));
            }
        }
        #pragma unroll
        for (int nt = 0; nt < 2; nt++) {
            float e0, e1; upk2(ev[nt], e0, e1);
            int c0 = 8*nt + 2*tg;
            AUG[wid*272 + c0*17 + n]     = y[nt][2*rh]   * e0;   // (M^T)[o][n]
            AUG[wid*272 + (c0+1)*17 + n] = y[nt][2*rh+1] * e1;
        }
    }
    __syncwarp();   // warp wid owns matrix wid end-to-end

    // -------- cofactors: register LU; both 16-lane segments compute matrix wid (seg 0 writes) --------
    const unsigned FULL = 0xffffffffu;
    const int seg = lane >> 4;
    const int o   = lane & 15;

    float a[17];
    {
        const float* Ma = AUG + wid * 272 + o * 17;
        #pragma unroll
        for (int j = 0; j < 16; j++) a[j] = Ma[j];
        a[16] = (o == 0) ? 1.f : 0.f;
    }
    float det = 1.f;

    #pragma unroll
    for (int k = 0; k < 16; k++) {
        float v = (o >= k) ? fabsf(a[k]) : -1.f;
        int   p = o;
        #pragma unroll
        for (int off = 8; off; off >>= 1) {
            float ov = __shfl_xor_sync(FULL, v, off, 16);
            int   oq = __shfl_xor_sync(FULL, p, off, 16);
            if (ov > v || (ov == v && oq < p)) { v = ov; p = oq; }
        }
        float pvk = __shfl_sync(FULL, a[k], p, 16);
        float kvk = __shfl_sync(FULL, a[k], k, 16);
        if (o == k) a[k] = pvk; else if (o == p) a[k] = kvk;
        det = (p != k) ? -det : det;
        det *= pvk;
        float mlt = (o > k) ? a[k] * rcp_ap(pvk) : 0.f;
        #pragma unroll
        for (int j = k + 1; j < 17; j++) {
            float pv = __shfl_sync(FULL, a[j], p, 16);
            float kv = __shfl_sync(FULL, a[j], k, 16);
            if (o == k) a[j] = pv; else if (o == p) a[j] = kv;
            a[j] -= mlt * pv;
        }
    }

    float z = 0.f, rhs = a[16];
    #pragma unroll
    for (int k = 15; k >= 0; k--) {
        float num = __shfl_sync(FULL, rhs,  k, 16);
        float den = __shfl_sync(FULL, a[k], k, 16);
        float xk = num * rcp_ap(den);
        if (o == k) z = xk;
        rhs -= a[k] * xk;
    }

    if (seg == 0) {
        float c0v = AUG[wid * 272 + o];   // M[o][0]
        out[((size_t)(b0 + wid) * 2 + s) * 16 + o] = c0v * det * z;
    }
}

extern "C" void kernel_launch(void* const* d_in, const int* in_sizes, int n_in,
                              void* d_out, int out_size)
{
    const float* eq  = (const float*)d_in[0];
    const float* rei = (const float*)d_in[1];
    const float* W   = (const float*)d_in[2];
    const float* b   = (const float*)d_in[3];
    const float* ed  = (const float*)d_in[4];
    const float* ei  = (const float*)d_in[5];
    float* out = (float*)d_out;

    int B = in_sizes[0] / (32 * 256);        // 4096
    cudaFuncSetAttribute(ocae11, cudaFuncAttributeMaxDynamicSharedMemorySize, SMEM_BYTES);
    dim3 grid((B / 8) * 2);                  // 1024 blocks
    ocae11<<<grid, THREADS, SMEM_BYTES>>>(eq, rei, W, b, ed, ei, out);
}